// round 14
// baseline (speedup 1.0000x reference)
#include <cuda_runtime.h>

#define Fn 640
#define Vn 322
#define EPSf 1e-8f
#define HALF_BIGf 5e9f
#define FOCALf 3.73205080756887729f
#define NTILE 256            // 16x16 tiles of 16x16 pixels
#define NSEG 4               // co-blocks per tile (round-robin face split)
#define SEGF 160             // faces per segment (640/4)
#define SEGP (SEGF + 8)      // padded for chunk-of-8 raster loop

// -------- device-global scratch (zero-init at load; counters are monotonic,
//          g_seg/g_partial fully rewritten every replay -> graph-safe) --------
__device__ float4 g_seg[NSEG * 65536];      // {w0, w1, fid_bits, zbits}
__device__ int    g_tiledone[NTILE];        // monotonic, check (old & 3) == 3
__device__ double g_partial[NTILE];
__device__ unsigned int g_rcount;           // monotonic, check (old & 255) == 255

__device__ __forceinline__ float tanh_mufu(float x) {
    float y;
    asm("tanh.approx.f32 %0, %1;" : "=f"(y) : "f"(x));
    return y;
}

struct __align__(16) FaceRec {              // one 48B record: 1 address stream
    float4 A;                               // w0x w0y w0c w1x
    float4 B;                               // w1y w1c zx  zy
    float  zc;
    unsigned fid;
    float  pad0, pad1;
};

__global__ void __launch_bounds__(256) fused_kernel(const float* __restrict__ verts,
                                                    const int*   __restrict__ faces,
                                                    const float* __restrict__ tex,
                                                    const float* __restrict__ ref,
                                                    const float* __restrict__ angle,
                                                    float* __restrict__ out) {
    __shared__ float  sx[Vn], sy[Vn], sd[Vn];
    __shared__ FaceRec sF[SEGF];            // unsorted compacted records
    __shared__ FaceRec sG[SEGP];            // sorted by tile-min-z (+ sentinels)
    __shared__ float  skey[SEGF];           // unsorted keys
    __shared__ float  skeyS[SEGP];          // sorted keys (+ sentinels)
    __shared__ int swcnt[5];
    __shared__ int sn;
    __shared__ double ss[8];
    __shared__ int sflag;

    int b = blockIdx.x, tid = threadIdx.x;
    int tile = b >> 2, seg = b & 3;
    int tx = tile & 15, ty = tile >> 4;

    // ---- vertex transform (all verts; MUFU sincos) ----
    float th = angle[0] * 6.28318530717958647692f;
    float c = __cosf(th), s = __sinf(th);
    for (int v = tid; v < Vn; v += 256) {
        float x = verts[3 * v], y = verts[3 * v + 1], z = verts[3 * v + 2];
        float xr = c * x + s * z;
        float zr = -s * x + c * z;
        float depth = 2.732f - zr;
        float invd = 1.0f / depth;
        sx[v] = FOCALf * xr * invd;
        sy[v] = FOCALf * y * invd;
        sd[v] = depth;
    }
    __syncthreads();

    // ---- plane compute + SAT cull (edges + bbox) + ordered compact ----
    float cxt = (float)(tx * 16 + 8) / 128.0f - 1.0f;
    float cyt = 1.0f - (float)(ty * 16 + 8) / 128.0f;
    const float hext = 7.5f / 128.0f;
    float txmin = (float)(tx * 16) / 128.0f + 0.5f / 128.0f - 1.0f;
    float txmax = txmin + 15.0f / 128.0f;
    float tymax = 1.0f - ((float)(ty * 16) / 128.0f + 0.5f / 128.0f);
    float tymin = tymax - 15.0f / 128.0f;

    bool pass = false;
    float4 A, B;
    float Zc = 0.f;
    int f = 4 * tid + seg;                   // round-robin: balances seg straggler
    if (tid < SEGF) {
        int i0 = faces[3 * f], i1 = faces[3 * f + 1], i2 = faces[3 * f + 2];
        float ax = sx[i0], ay = sy[i0];
        float bx = sx[i1], by = sy[i1];
        float cx = sx[i2], cy = sy[i2];
        float area = (bx - ax) * (cy - ay) - (by - ay) * (cx - ax);
        bool valid = fabsf(area) > EPSf;            // NaN -> invalid, matches jnp
        float inv = 1.0f / (valid ? area : 1.0f);
        float e0x = cx - bx, e0y = cy - by;
        float w0x = -e0y * inv, w0y = e0x * inv, w0c = (e0y * bx - e0x * by) * inv;
        float e1x = ax - cx, e1y = ay - cy;
        float w1x = -e1y * inv, w1y = e1x * inv, w1c = (e1y * cx - e1x * cy) * inv;
        if (!valid) { w0x = 0.f; w0y = 0.f; w0c = -1e30f; w1x = 0.f; w1y = 0.f; w1c = 0.f; }
        float d0 = sd[i0], d1 = sd[i1], d2 = sd[i2];
        float e02 = d0 - d2, e12 = d1 - d2;
        float zx = w0x * e02 + w1x * e12;
        float zy = w0y * e02 + w1y * e12;
        float zc = d2 + w0c * e02 + w1c * e12;
        A = make_float4(w0x, w0y, w0c, w1x);
        B = make_float4(w1y, w1c, zx, zy);
        Zc = zc;
        // dilated edge half-planes
        float w2x = -(w0x + w1x), w2y = -(w0y + w1y), w2c = 1.0f - w0c - w1c;
        float v0 = fmaf(w0x, cxt, fmaf(w0y, cyt, w0c));
        float m0 = (fabsf(w0x) + fabsf(w0y)) * hext
                 + 1e-5f * (fabsf(w0x) + fabsf(w0y) + fabsf(w0c));
        float v1 = fmaf(w1x, cxt, fmaf(w1y, cyt, w1c));
        float m1 = (fabsf(w1x) + fabsf(w1y)) * hext
                 + 1e-5f * (fabsf(w1x) + fabsf(w1y) + fabsf(w1c));
        float v2 = fmaf(w2x, cxt, fmaf(w2y, cyt, w2c));
        float m2 = (fabsf(w2x) + fabsf(w2y)) * hext
                 + 1e-5f * (fabsf(w2x) + fabsf(w2y) + fabsf(w2c));
        pass = (v0 + m0 >= 0.f) & (v1 + m1 >= 0.f) & (v2 + m2 >= 0.f);
        // triangle bbox vs tile bbox (caps skinny-triangle miter spikes)
        float bxmin = fminf(ax, fminf(bx, cx)), bxmax = fmaxf(ax, fmaxf(bx, cx));
        float bymin = fminf(ay, fminf(by, cy)), bymax = fmaxf(ay, fmaxf(by, cy));
        pass = pass & (bxmax >= txmin - 1e-4f) & (bxmin <= txmax + 1e-4f)
                    & (bymax >= tymin - 1e-4f) & (bymin <= tymax + 1e-4f);
    }
    unsigned mask = __ballot_sync(0xffffffffu, pass);
    int w = tid >> 5, lane = tid & 31;
    if (lane == 0 && w < 5) swcnt[w] = __popc(mask);
    __syncthreads();
    if (pass) {
        int off = __popc(mask & ((1u << lane) - 1u));
        for (int i = 0; i < w; i++) off += swcnt[i];   // warp order = ascending f
        sF[off].A = A;
        sF[off].B = B;
        sF[off].zc = Zc;
        sF[off].fid = (unsigned)f;
        // conservative tile-min of the z plane (corner of box, minus margin)
        float zcen = fmaf(B.z, cxt, fmaf(B.w, cyt, Zc));
        float zmar = (fabsf(B.z) + fabsf(B.w)) * hext
                   + 1e-5f * (fabsf(B.z) + fabsf(B.w) + fabsf(Zc));
        skey[off] = zcen - zmar;
    }
    if (tid == 0) sn = swcnt[0] + swcnt[1] + swcnt[2] + swcnt[3] + swcnt[4];
    __syncthreads();
    int n = sn;
    int npad = (n + 7) & ~7;

    // ---- deterministic rank-sort by (minz, slot) + sentinel padding ----
    if (tid < n) {
        float myk = skey[tid];
        int rank = 0;
        for (int j = 0; j < n; j++) {
            float kj = skey[j];
            rank += (kj < myk) || (kj == myk && j < tid);
        }
        sG[rank] = sF[tid];
        skeyS[rank] = myk;
    }
    for (int j = n + tid; j < npad; j += 256) {        // sentinels: never taken
        sG[j].A = make_float4(0.f, 0.f, -1e30f, 0.f);
        sG[j].B = make_float4(0.f, 0.f, 0.f, 0.f);
        sG[j].zc = 0.f;
        sG[j].fid = 0xFFFFFFFFu;
        skeyS[j] = 1e30f;
    }
    __syncthreads();

    // ---- raster: front-to-back, chunk-of-8 conservative break ----
    int x = tx * 16 + (tid & 15);
    int y = ty * 16 + (tid >> 4);
    int p = y * 256 + x;
    float px = (x + 0.5f) / 128.0f - 1.0f;
    float py = 1.0f - (y + 0.5f) / 128.0f;

    unsigned long long bk = ((unsigned long long)__float_as_uint(HALF_BIGf)) << 32;
    float best = HALF_BIGf;
    int jw = -1;
    for (int j0 = 0; j0 < n; j0 += 8) {
        if (skeyS[j0] > best) break;         // chunk head = chunk min (sorted): sound
#pragma unroll
        for (int jj = 0; jj < 8; jj++) {     // branch-free body: full ILP
            int j = j0 + jj;
            float4 Aj = sG[j].A;
            float4 Bj = sG[j].B;
            float  zc = sG[j].zc;
            unsigned fj = sG[j].fid;
            float w0 = fmaf(Aj.x, px, fmaf(Aj.y, py, Aj.z));
            float w1 = fmaf(Aj.w, px, fmaf(Bj.x, py, Bj.y));
            float z  = fmaf(Bj.z, px, fmaf(Bj.w, py, zc));
            float w2 = 1.0f - w0 - w1;       // exact reference formula
            float m  = fminf(fminf(w0, w1), w2);
            // (zbits, fid) key-min == jnp.argmin first-min tie-break, order-free
            unsigned long long k =
                (((unsigned long long)__float_as_uint(z)) << 32) | fj;
            bool take = (m >= 0.f) & (z > EPSf) & (k < bk);
            if (take) { bk = k; best = z; jw = j; }
        }
    }
    float bw0 = 0.f, bw1 = 0.f;
    if (jw >= 0) {                           // direct winner fetch (no rescan)
        float4 Aj = sG[jw].A;
        float4 Bj = sG[jw].B;
        bw0 = fmaf(Aj.x, px, fmaf(Aj.y, py, Aj.z));
        bw1 = fmaf(Aj.w, px, fmaf(Bj.x, py, Bj.y));
    }
    g_seg[(seg << 16) + p] = make_float4(
        bw0, bw1, __uint_as_float((unsigned)(bk & 0xFFFFFFFFu)),
        __uint_as_float((unsigned)(bk >> 32)));
    __syncthreads();                         // orders all block's writes before tid0's fence
    if (tid == 0) {
        __threadfence();                     // single release fence for the whole block
        int old = atomicAdd(&g_tiledone[tile], 1);
        sflag = ((old & 3) == 3);            // last co-block (mod-4: replay-safe)
        if (sflag) __threadfence();          // acquire: see peer blocks' g_seg writes
    }
    __syncthreads();
    if (!sflag) return;

    // ---- epilogue: merge 4 segments, shade (MUFU tanh), loss ----
    unsigned long long bk2 = 0xFFFFFFFFFFFFFFFFull;
    float w0 = 0.f, w1 = 0.f;
#pragma unroll
    for (int sg = 0; sg < NSEG; sg++) {
        float4 v = __ldcg(&g_seg[(sg << 16) + p]);
        unsigned long long k =
            (((unsigned long long)__float_as_uint(v.w)) << 32) | __float_as_uint(v.z);
        if (k < bk2) { bk2 = k; w0 = v.x; w1 = v.y; }   // (z, fid) lexicographic min
    }
    float col0 = 0.f, col1 = 0.f, col2 = 0.f;
    if ((unsigned)(bk2 >> 32) < __float_as_uint(HALF_BIGf)) {
        int fw = (int)(unsigned)(bk2 & 0xFFFFFFFFu);
        float pw[3] = { w0, w1, 1.0f - w0 - w1 };
        int   i0c[3];
        float fr[3];
#pragma unroll
        for (int k = 0; k < 3; k++) {
            float u  = fminf(fmaxf(pw[k], 0.f), 1.f) * 3.0f;
            float fl = fminf(fmaxf(floorf(u), 0.f), 2.f);
            i0c[k] = (int)fl;
            fr[k] = u - fl;
        }
        const float* tb = tex + fw * 192;
#pragma unroll
        for (int a = 0; a < 2; a++)
#pragma unroll
            for (int bb = 0; bb < 2; bb++)
#pragma unroll
                for (int cc = 0; cc < 2; cc++) {
                    float wc = (a  ? fr[0] : 1.f - fr[0])
                             * (bb ? fr[1] : 1.f - fr[1])
                             * (cc ? fr[2] : 1.f - fr[2]);
                    int idx = ((i0c[0] + a) * 16 + (i0c[1] + bb) * 4 + (i0c[2] + cc)) * 3;
                    col0 += wc * tanh_mufu(__ldg(tb + idx + 0));
                    col1 += wc * tanh_mufu(__ldg(tb + idx + 1));
                    col2 += wc * tanh_mufu(__ldg(tb + idx + 2));
                }
    }
    float d0 = col0 - ref[p];
    float d1 = col1 - ref[65536 + p];
    float d2 = col2 - ref[131072 + p];
    double sum = (double)d0 * d0 + (double)d1 * d1 + (double)d2 * d2;

#pragma unroll
    for (int o = 16; o; o >>= 1) sum += __shfl_down_sync(0xffffffffu, sum, o);
    if (lane == 0) ss[w] = sum;
    __syncthreads();
    if (tid == 0) {
        double t = 0.0;
        for (int i = 0; i < 8; i++) t += ss[i];
        g_partial[tile] = t;
        __threadfence();                     // release g_partial
        unsigned old = atomicAdd(&g_rcount, 1u);
        sflag = ((old & 255) == 255);        // very last tile (mod-256: replay-safe)
        if (sflag) __threadfence();          // acquire
    }
    __syncthreads();
    if (sflag) {                             // fixed-order deterministic final reduce
        double v = __ldcg(&g_partial[tid]);
#pragma unroll
        for (int o = 16; o; o >>= 1) v += __shfl_down_sync(0xffffffffu, v, o);
        if (lane == 0) ss[w] = v;
        __syncthreads();
        if (tid == 0) {
            double t = 0.0;
            for (int i = 0; i < 8; i++) t += ss[i];
            out[0] = (float)t;
        }
    }
}

extern "C" void kernel_launch(void* const* d_in, const int* in_sizes, int n_in,
                              void* d_out, int out_size) {
    const float* verts = (const float*)d_in[0];   // (1,322,3)
    const int*   faces = (const int*)  d_in[1];   // (1,640,3)
    const float* tex   = (const float*)d_in[2];   // (1,640,4,4,4,3)
    const float* ref   = (const float*)d_in[3];   // (1,3,256,256)
    const float* angle = (const float*)d_in[4];   // (1,)

    fused_kernel<<<NTILE * NSEG, 256>>>(verts, faces, tex, ref, angle, (float*)d_out);
}

// round 15
// speedup vs baseline: 1.1518x; 1.1518x over previous
#include <cuda_runtime.h>

#define Fn 640
#define Vn 322
#define EPSf 1e-8f
#define HALF_BIGf 5e9f
#define FOCALf 3.73205080756887729f
#define NTILE 256            // 16x16 tiles of 16x16 pixels
#define NSEG 2               // co-blocks per tile (round-robin face split)
#define SEGF 320             // faces per segment (640/2)

// -------- device-global scratch (zero-init at load; counters are monotonic,
//          g_seg/g_partial fully rewritten every replay -> graph-safe) --------
__device__ float4 g_seg[NSEG * 65536];      // {w0, w1, fid_bits, zbits}
__device__ int    g_tiledone[NTILE];        // monotonic, check (old & 1) == 1
__device__ double g_partial[NTILE];
__device__ unsigned int g_rcount;           // monotonic, check (old & 255) == 255

__device__ __forceinline__ float tanh_mufu(float x) {
    float y;
    asm("tanh.approx.f32 %0, %1;" : "=f"(y) : "f"(x));
    return y;
}

struct __align__(16) FaceRec {              // one 48B record: 1 address stream
    float4 A;                               // w0x w0y w0c w1x
    float4 B;                               // w1y w1c zx  zy
    float  zc;
    unsigned fid;
    float  pad0, pad1;
};

__global__ void __launch_bounds__(256) fused_kernel(const float* __restrict__ verts,
                                                    const int*   __restrict__ faces,
                                                    const float* __restrict__ tex,
                                                    const float* __restrict__ ref,
                                                    const float* __restrict__ angle,
                                                    float* __restrict__ out) {
    __shared__ float  sx[Vn], sy[Vn], sd[Vn];
    __shared__ FaceRec sF[SEGF];            // unsorted compacted records
    __shared__ FaceRec sG[SEGF];            // sorted by tile-min-z
    __shared__ float  skey[SEGF];           // unsorted keys
    __shared__ float  skeyS[SEGF];          // sorted keys
    __shared__ int sn;
    __shared__ double ss[8];
    __shared__ int sflag;

    int b = blockIdx.x, tid = threadIdx.x;
    int tile = b >> 1, seg = b & 1;
    int tx = tile & 15, ty = tile >> 4;

    if (tid == 0) sn = 0;
    // ---- vertex transform (all verts; MUFU sincos) ----
    float th = angle[0] * 6.28318530717958647692f;
    float c = __cosf(th), s = __sinf(th);
    for (int v = tid; v < Vn; v += 256) {
        float x = verts[3 * v], y = verts[3 * v + 1], z = verts[3 * v + 2];
        float xr = c * x + s * z;
        float zr = -s * x + c * z;
        float depth = 2.732f - zr;
        float invd = 1.0f / depth;
        sx[v] = FOCALf * xr * invd;
        sy[v] = FOCALf * y * invd;
        sd[v] = depth;
    }
    __syncthreads();

    // ---- plane compute + SAT cull (edges + bbox) + atomic compact ----
    // (compaction order is irrelevant: winner = (z,fid) key-min, order-free)
    float cxt = (float)(tx * 16 + 8) / 128.0f - 1.0f;
    float cyt = 1.0f - (float)(ty * 16 + 8) / 128.0f;
    const float hext = 7.5f / 128.0f;
    float txmin = (float)(tx * 16) / 128.0f + 0.5f / 128.0f - 1.0f;
    float txmax = txmin + 15.0f / 128.0f;
    float tymax = 1.0f - ((float)(ty * 16) / 128.0f + 0.5f / 128.0f);
    float tymin = tymax - 15.0f / 128.0f;

    for (int j = tid; j < SEGF; j += 256) {
        int f = 2 * j + seg;                 // round-robin: balances seg straggler
        int i0 = faces[3 * f], i1 = faces[3 * f + 1], i2 = faces[3 * f + 2];
        float ax = sx[i0], ay = sy[i0];
        float bx = sx[i1], by = sy[i1];
        float cx = sx[i2], cy = sy[i2];
        float area = (bx - ax) * (cy - ay) - (by - ay) * (cx - ax);
        bool valid = fabsf(area) > EPSf;            // NaN -> invalid, matches jnp
        float inv = 1.0f / (valid ? area : 1.0f);
        float e0x = cx - bx, e0y = cy - by;
        float w0x = -e0y * inv, w0y = e0x * inv, w0c = (e0y * bx - e0x * by) * inv;
        float e1x = ax - cx, e1y = ay - cy;
        float w1x = -e1y * inv, w1y = e1x * inv, w1c = (e1y * cx - e1x * cy) * inv;
        if (!valid) { w0x = 0.f; w0y = 0.f; w0c = -1e30f; w1x = 0.f; w1y = 0.f; w1c = 0.f; }
        // dilated edge half-planes
        float w2x = -(w0x + w1x), w2y = -(w0y + w1y), w2c = 1.0f - w0c - w1c;
        float v0 = fmaf(w0x, cxt, fmaf(w0y, cyt, w0c));
        float m0 = (fabsf(w0x) + fabsf(w0y)) * hext
                 + 1e-5f * (fabsf(w0x) + fabsf(w0y) + fabsf(w0c));
        float v1 = fmaf(w1x, cxt, fmaf(w1y, cyt, w1c));
        float m1 = (fabsf(w1x) + fabsf(w1y)) * hext
                 + 1e-5f * (fabsf(w1x) + fabsf(w1y) + fabsf(w1c));
        float v2 = fmaf(w2x, cxt, fmaf(w2y, cyt, w2c));
        float m2 = (fabsf(w2x) + fabsf(w2y)) * hext
                 + 1e-5f * (fabsf(w2x) + fabsf(w2y) + fabsf(w2c));
        bool pass = (v0 + m0 >= 0.f) & (v1 + m1 >= 0.f) & (v2 + m2 >= 0.f);
        // triangle bbox vs tile bbox (caps skinny-triangle miter spikes)
        float bxmin = fminf(ax, fminf(bx, cx)), bxmax = fmaxf(ax, fmaxf(bx, cx));
        float bymin = fminf(ay, fminf(by, cy)), bymax = fmaxf(ay, fmaxf(by, cy));
        pass = pass & (bxmax >= txmin - 1e-4f) & (bxmin <= txmax + 1e-4f)
                    & (bymax >= tymin - 1e-4f) & (bymin <= tymax + 1e-4f);
        if (pass) {
            int slot = atomicAdd(&sn, 1);
            float d0 = sd[i0], d1 = sd[i1], d2 = sd[i2];
            float e02 = d0 - d2, e12 = d1 - d2;
            float zx = w0x * e02 + w1x * e12;
            float zy = w0y * e02 + w1y * e12;
            float zc = d2 + w0c * e02 + w1c * e12;
            sF[slot].A = make_float4(w0x, w0y, w0c, w1x);
            sF[slot].B = make_float4(w1y, w1c, zx, zy);
            sF[slot].zc = zc;
            sF[slot].fid = (unsigned)f;
            // conservative tile-min of the z plane
            float zcen = fmaf(zx, cxt, fmaf(zy, cyt, zc));
            float zmar = (fabsf(zx) + fabsf(zy)) * hext
                       + 1e-5f * (fabsf(zx) + fabsf(zy) + fabsf(zc));
            skey[slot] = zcen - zmar;
        }
    }
    __syncthreads();
    int n = sn;

    // ---- rank-sort by (minz, slot) and scatter (order only affects scan order,
    //      never the (z,fid) key-min result -> deterministic output) ----
    for (int i = tid; i < n; i += 256) {
        float myk = skey[i];
        int rank = 0;
        for (int j = 0; j < n; j++) {
            float kj = skey[j];
            rank += (kj < myk) || (kj == myk && j < i);
        }
        sG[rank] = sF[i];
        skeyS[rank] = myk;
    }
    __syncthreads();

    // ---- raster: front-to-back scan with per-face conservative break ----
    int x = tx * 16 + (tid & 15);
    int y = ty * 16 + (tid >> 4);
    int p = y * 256 + x;
    float px = (x + 0.5f) / 128.0f - 1.0f;
    float py = 1.0f - (y + 0.5f) / 128.0f;

    unsigned long long bk = ((unsigned long long)__float_as_uint(HALF_BIGf)) << 32;
    float best = HALF_BIGf;
    int jw = -1;
#pragma unroll 4
    for (int j = 0; j < n; j++) {
        if (skeyS[j] > best) break;          // sound: minz_cons <= z at any tile pixel
        float4 Aj = sG[j].A;
        float4 Bj = sG[j].B;
        float  zc = sG[j].zc;
        unsigned fj = sG[j].fid;
        float w0 = fmaf(Aj.x, px, fmaf(Aj.y, py, Aj.z));
        float w1 = fmaf(Aj.w, px, fmaf(Bj.x, py, Bj.y));
        float z  = fmaf(Bj.z, px, fmaf(Bj.w, py, zc));
        float w2 = 1.0f - w0 - w1;           // exact reference formula
        float m  = fminf(fminf(w0, w1), w2);
        // (zbits, fid) key-min == jnp.argmin first-min tie-break, order-free
        unsigned long long k =
            (((unsigned long long)__float_as_uint(z)) << 32) | fj;
        bool take = (m >= 0.f) & (z > EPSf) & (k < bk);
        if (take) { bk = k; best = z; jw = j; }
    }
    float bw0 = 0.f, bw1 = 0.f;
    if (jw >= 0) {                           // direct winner fetch (no rescan)
        float4 Aj = sG[jw].A;
        float4 Bj = sG[jw].B;
        bw0 = fmaf(Aj.x, px, fmaf(Aj.y, py, Aj.z));
        bw1 = fmaf(Aj.w, px, fmaf(Bj.x, py, Bj.y));
    }
    g_seg[(seg << 16) + p] = make_float4(
        bw0, bw1, __uint_as_float((unsigned)(bk & 0xFFFFFFFFu)),
        __uint_as_float((unsigned)(bk >> 32)));
    __syncthreads();                         // orders all block's writes before tid0's fence
    if (tid == 0) {
        __threadfence();                     // single release fence for the whole block
        int old = atomicAdd(&g_tiledone[tile], 1);
        sflag = ((old & 1) == 1);            // last co-block (mod-2: replay-safe)
        if (sflag) __threadfence();          // acquire: see peer block's g_seg writes
    }
    __syncthreads();
    if (!sflag) return;

    // ---- epilogue: merge 2 segments, shade (MUFU tanh), loss ----
    int w = tid >> 5, lane = tid & 31;
    unsigned long long bk2 = 0xFFFFFFFFFFFFFFFFull;
    float w0 = 0.f, w1 = 0.f;
#pragma unroll
    for (int sg = 0; sg < NSEG; sg++) {
        float4 v = __ldcg(&g_seg[(sg << 16) + p]);
        unsigned long long k =
            (((unsigned long long)__float_as_uint(v.w)) << 32) | __float_as_uint(v.z);
        if (k < bk2) { bk2 = k; w0 = v.x; w1 = v.y; }   // (z, fid) lexicographic min
    }
    float col0 = 0.f, col1 = 0.f, col2 = 0.f;
    if ((unsigned)(bk2 >> 32) < __float_as_uint(HALF_BIGf)) {
        int fw = (int)(unsigned)(bk2 & 0xFFFFFFFFu);
        float pw[3] = { w0, w1, 1.0f - w0 - w1 };
        int   i0c[3];
        float fr[3];
#pragma unroll
        for (int k = 0; k < 3; k++) {
            float u  = fminf(fmaxf(pw[k], 0.f), 1.f) * 3.0f;
            float fl = fminf(fmaxf(floorf(u), 0.f), 2.f);
            i0c[k] = (int)fl;
            fr[k] = u - fl;
        }
        const float* tb = tex + fw * 192;
#pragma unroll
        for (int a = 0; a < 2; a++)
#pragma unroll
            for (int bb = 0; bb < 2; bb++)
#pragma unroll
                for (int cc = 0; cc < 2; cc++) {
                    float wc = (a  ? fr[0] : 1.f - fr[0])
                             * (bb ? fr[1] : 1.f - fr[1])
                             * (cc ? fr[2] : 1.f - fr[2]);
                    int idx = ((i0c[0] + a) * 16 + (i0c[1] + bb) * 4 + (i0c[2] + cc)) * 3;
                    col0 += wc * tanh_mufu(__ldg(tb + idx + 0));
                    col1 += wc * tanh_mufu(__ldg(tb + idx + 1));
                    col2 += wc * tanh_mufu(__ldg(tb + idx + 2));
                }
    }
    float d0 = col0 - ref[p];
    float d1 = col1 - ref[65536 + p];
    float d2 = col2 - ref[131072 + p];
    double sum = (double)d0 * d0 + (double)d1 * d1 + (double)d2 * d2;

#pragma unroll
    for (int o = 16; o; o >>= 1) sum += __shfl_down_sync(0xffffffffu, sum, o);
    if (lane == 0) ss[w] = sum;
    __syncthreads();
    if (tid == 0) {
        double t = 0.0;
        for (int i = 0; i < 8; i++) t += ss[i];
        g_partial[tile] = t;
        __threadfence();                     // release g_partial
        unsigned old = atomicAdd(&g_rcount, 1u);
        sflag = ((old & 255) == 255);        // very last tile (mod-256: replay-safe)
        if (sflag) __threadfence();          // acquire
    }
    __syncthreads();
    if (sflag) {                             // fixed-order deterministic final reduce
        double v = __ldcg(&g_partial[tid]);
#pragma unroll
        for (int o = 16; o; o >>= 1) v += __shfl_down_sync(0xffffffffu, v, o);
        if (lane == 0) ss[w] = v;
        __syncthreads();
        if (tid == 0) {
            double t = 0.0;
            for (int i = 0; i < 8; i++) t += ss[i];
            out[0] = (float)t;
        }
    }
}

extern "C" void kernel_launch(void* const* d_in, const int* in_sizes, int n_in,
                              void* d_out, int out_size) {
    const float* verts = (const float*)d_in[0];   // (1,322,3)
    const int*   faces = (const int*)  d_in[1];   // (1,640,3)
    const float* tex   = (const float*)d_in[2];   // (1,640,4,4,4,3)
    const float* ref   = (const float*)d_in[3];   // (1,3,256,256)
    const float* angle = (const float*)d_in[4];   // (1,)

    fused_kernel<<<NTILE * NSEG, 256>>>(verts, faces, tex, ref, angle, (float*)d_out);
}